// round 12
// baseline (speedup 1.0000x reference)
#include <cuda_runtime.h>
#include <cstdint>

// ---------------- problem constants ----------------
#define BB   16
#define CC   256
#define HH   64
#define WW   64
#define NHH  8
#define DHH  64
#define CIN  260
#define KPAD 264
#define DQKV 512
#define HWN  4096
#define PLEN 128
#define SCALE 0.08838834764831843f  // 1/sqrt(128)

typedef unsigned long long u64;

// ---------------- f32x2 packed-FMA helpers ----------------
__device__ __forceinline__ u64 pk2(float x) {
    u64 r; asm("mov.b64 %0, {%1, %1};" : "=l"(r) : "f"(x)); return r;
}
__device__ __forceinline__ void fma2(u64 &d, u64 a, u64 b) {
    asm("fma.rn.f32x2 %0, %1, %2, %3;" : "=l"(d) : "l"(a), "l"(b), "l"(d));
}
__device__ __forceinline__ float2 up2(u64 v) {
    float lo, hi; asm("mov.b64 {%0, %1}, %2;" : "=f"(lo), "=f"(hi) : "l"(v));
    return make_float2(lo, hi);
}

// ---------------- tf32 helpers ----------------
__device__ __forceinline__ uint32_t f2tf32(float f) {
    uint32_t u;
    asm("cvt.rna.tf32.f32 %0, %1;" : "=r"(u) : "f"(f));
    return u;
}
__device__ __forceinline__ void mma_tf32(float c[4], const uint32_t a[4],
                                         const uint32_t bfr[2]) {
    asm volatile(
        "mma.sync.aligned.m16n8k8.row.col.f32.tf32.tf32.f32 "
        "{%0,%1,%2,%3}, {%4,%5,%6,%7}, {%8,%9}, {%0,%1,%2,%3};"
        : "+f"(c[0]), "+f"(c[1]), "+f"(c[2]), "+f"(c[3])
        : "r"(a[0]), "r"(a[1]), "r"(a[2]), "r"(a[3]),
          "r"(bfr[0]), "r"(bfr[1]));
}

// ---------------- device scratch ----------------
#define TSZ ((size_t)BB * DQKV * HWN)
__device__ float g_Q [TSZ];
__device__ float g_K [TSZ];
__device__ float g_V [TSZ];
__device__ float g_QT[TSZ];
__device__ float g_KT[TSZ];
__device__ float g_VT[TSZ];
__device__ float g_A [TSZ];    // a_w in [b][p][ch]
__device__ float g_AT[TSZ];    // a_h in [b][p][ch]
__device__ float g_P [(size_t)BB * NHH * HH * WW * PLEN];   // RAW scaled logits
__device__ float g_XT[(size_t)BB * HWN * KPAD];

// =====================================================================
// Kernel 0: transpose xp = concat(x,pos) -> g_XT [b][p][264]
// =====================================================================
__global__ __launch_bounds__(256) void xpose_x(
    const float* __restrict__ x, const float* __restrict__ pos)
{
    __shared__ float tile[64][65];
    int t = threadIdx.x;
    int p0 = blockIdx.x * 64, c0 = blockIdx.y * 64, b = blockIdx.z;
    #pragma unroll
    for (int r = 0; r < 16; r++) {
        int idx = r * 256 + t;
        int cc = idx >> 6, pp = idx & 63;
        int c = c0 + cc;
        float v = 0.0f;
        if (c < CC)       v = x[((size_t)b * CC + c) * HWN + p0 + pp];
        else if (c < CIN) v = pos[(size_t)(c - CC) * HWN + p0 + pp];
        tile[cc][pp] = v;
    }
    __syncthreads();
    #pragma unroll
    for (int r = 0; r < 16; r++) {
        int idx = r * 256 + t;
        int pp = idx >> 6, cc = idx & 63;
        int c = c0 + cc;
        if (c < KPAD)
            g_XT[((size_t)b * HWN + p0 + pp) * KPAD + c] = tile[cc][pp];
    }
}

// =====================================================================
// Kernel 1: QKV projection via mma.sync tf32 (m16n8k8).
// =====================================================================
__global__ __launch_bounds__(256, 2) void qkv_mma(
    const float* __restrict__ Wq, const float* __restrict__ bq,
    const float* __restrict__ Wk, const float* __restrict__ bk,
    const float* __restrict__ Wv, const float* __restrict__ bv)
{
    int pT = blockIdx.x, nT = blockIdx.y, b = blockIdx.z;
    int which = nT >> 2;
    int mOff  = (nT & 3) * 128;
    const float* Wt   = (which == 0) ? Wq : (which == 1) ? Wk : Wv;
    const float* bias = (which == 0) ? bq : (which == 1) ? bk : bv;
    float*       outp = (which == 0) ? g_Q : (which == 1) ? g_K : g_V;

    __shared__ uint32_t As[128][36];
    __shared__ uint32_t Bs[128][36];

    int t = threadIdx.x, lane = t & 31, wid = t >> 5;
    int g = lane >> 2, tig = lane & 3;
    int wm = (wid >> 2) * 64, wn = (wid & 3) * 32;

    const float* xt = g_XT + ((size_t)b * HWN + (size_t)pT * 128) * KPAD;

    float c[4][4][4];
    #pragma unroll
    for (int mi = 0; mi < 4; mi++)
        #pragma unroll
        for (int ni = 0; ni < 4; ni++)
            #pragma unroll
            for (int e = 0; e < 4; e++) c[mi][ni][e] = 0.0f;

    for (int c0 = 0; c0 < 9; c0++) {
        int kBase = c0 * 32;
        #pragma unroll
        for (int r = 0; r < 4; r++) {
            int idx = r * 256 + t;
            int row = idx >> 3, q = idx & 7;
            int k4 = kBase + q * 4;
            float4 va = make_float4(0.f, 0.f, 0.f, 0.f);
            if (k4 <= CIN - 4)
                va = *(const float4*)(Wt + (size_t)(mOff + row) * CIN + k4);
            As[row][q * 4 + 0] = f2tf32(va.x);
            As[row][q * 4 + 1] = f2tf32(va.y);
            As[row][q * 4 + 2] = f2tf32(va.z);
            As[row][q * 4 + 3] = f2tf32(va.w);
            float4 vb = make_float4(0.f, 0.f, 0.f, 0.f);
            if (k4 <= KPAD - 4)
                vb = *(const float4*)(xt + (size_t)row * KPAD + k4);
            Bs[row][q * 4 + 0] = f2tf32(vb.x);
            Bs[row][q * 4 + 1] = f2tf32(vb.y);
            Bs[row][q * 4 + 2] = f2tf32(vb.z);
            Bs[row][q * 4 + 3] = f2tf32(vb.w);
        }
        __syncthreads();
        #pragma unroll
        for (int ks = 0; ks < 4; ks++) {
            int kk = ks * 8;
            uint32_t a[4][4], bfr[4][2];
            #pragma unroll
            for (int mi = 0; mi < 4; mi++) {
                int row = wm + mi * 16 + g;
                a[mi][0] = As[row][kk + tig];
                a[mi][1] = As[row + 8][kk + tig];
                a[mi][2] = As[row][kk + tig + 4];
                a[mi][3] = As[row + 8][kk + tig + 4];
            }
            #pragma unroll
            for (int ni = 0; ni < 4; ni++) {
                int col = wn + ni * 8 + g;
                bfr[ni][0] = Bs[col][kk + tig];
                bfr[ni][1] = Bs[col][kk + tig + 4];
            }
            #pragma unroll
            for (int mi = 0; mi < 4; mi++)
                #pragma unroll
                for (int ni = 0; ni < 4; ni++)
                    mma_tf32(c[mi][ni], a[mi], bfr[ni]);
        }
        __syncthreads();
    }

    #pragma unroll
    for (int mi = 0; mi < 4; mi++) {
        int row0 = wm + mi * 16 + g;
        float bi0 = bias[mOff + row0];
        float bi1 = bias[mOff + row0 + 8];
        float* o0 = outp + ((size_t)b * DQKV + mOff + row0) * HWN + (size_t)pT * 128;
        float* o1 = o0 + (size_t)8 * HWN;
        #pragma unroll
        for (int ni = 0; ni < 4; ni++) {
            int col = wn + ni * 8 + tig * 2;
            float2 v0 = make_float2(c[mi][ni][0] + bi0, c[mi][ni][1] + bi0);
            float2 v1 = make_float2(c[mi][ni][2] + bi1, c[mi][ni][3] + bi1);
            *(float2*)(o0 + col) = v0;
            *(float2*)(o1 + col) = v1;
        }
    }
}

// =====================================================================
// Kernel 2: transpose each 64x64 image of Q,K,V -> QT,KT,VT
// =====================================================================
__global__ __launch_bounds__(256) void transpose3_kernel()
{
    const float* src = (blockIdx.y == 0) ? g_Q : (blockIdx.y == 1) ? g_K : g_V;
    float*       dst = (blockIdx.y == 0) ? g_QT : (blockIdx.y == 1) ? g_KT : g_VT;
    size_t base = (size_t)blockIdx.x * HWN;
    __shared__ float sm[64][65];
    int t = threadIdx.x;
    #pragma unroll
    for (int r = 0; r < 16; r++) {
        int idx = r * 256 + t;
        sm[idx >> 6][idx & 63] = src[base + idx];
    }
    __syncthreads();
    #pragma unroll
    for (int r = 0; r < 16; r++) {
        int idx = r * 256 + t;
        dst[base + idx] = sm[idx & 63][idx >> 6];
    }
}

// =====================================================================
// Kernel 3: row logits (f32x2). writes RAW scaled logits.
// =====================================================================
__global__ __launch_bounds__(256) void logits_row_kernel()
{
    int i = blockIdx.x, h = blockIdx.y, b = blockIdx.z;
    __shared__ float qs[64][64];
    __shared__ float ks[64][64];
    size_t base = ((size_t)(b * DQKV + h * DHH)) * HWN + i * WW;
    int t = threadIdx.x;
    #pragma unroll
    for (int r = 0; r < 16; r++) {
        int idx = r * 256 + t;
        int d = idx >> 6, j = idx & 63;
        qs[d][j] = g_Q[base + (size_t)d * HWN + j];
        ks[d][j] = g_K[base + (size_t)d * HWN + j];
    }
    __syncthreads();
    int tx = t & 15, ty = t >> 4;
    u64 acc[4][2];
    #pragma unroll
    for (int u = 0; u < 4; u++) { acc[u][0] = 0ull; acc[u][1] = 0ull; }
    #pragma unroll
    for (int d = 0; d < 64; d++) {
        float4 q4 = *(float4*)&qs[d][ty * 4];
        const u64* kp = (const u64*)&ks[d][tx * 4];
        u64 k0 = kp[0], k1 = kp[1];
        u64 qa[4] = {pk2(q4.x), pk2(q4.y), pk2(q4.z), pk2(q4.w)};
        #pragma unroll
        for (int u = 0; u < 4; u++) {
            fma2(acc[u][0], qa[u], k0);
            fma2(acc[u][1], qa[u], k1);
        }
    }
    size_t pbase = (((size_t)((b * NHH + h) * HH + i)) * WW) * PLEN;
    #pragma unroll
    for (int u = 0; u < 4; u++) {
        int j = ty * 4 + u;
        float2 p0 = up2(acc[u][0]), p1 = up2(acc[u][1]);
        float4 o = make_float4(p0.x * SCALE, p0.y * SCALE, p1.x * SCALE, p1.y * SCALE);
        *(float4*)&g_P[pbase + (size_t)j * PLEN + tx * 4] = o;
    }
}

// =====================================================================
// Kernel 4: column logits (f32x2). writes RAW scaled logits.
// =====================================================================
__global__ __launch_bounds__(256) void logits_col_kernel()
{
    int j = blockIdx.x, h = blockIdx.y, b = blockIdx.z;
    __shared__ float qs[64][64];
    __shared__ float ks[64][64];
    size_t base = ((size_t)(b * DQKV + h * DHH)) * HWN + j * HH;
    int t = threadIdx.x;
    #pragma unroll
    for (int r = 0; r < 16; r++) {
        int idx = r * 256 + t;
        int d = idx >> 6, ii = idx & 63;
        qs[d][ii] = g_QT[base + (size_t)d * HWN + ii];
        ks[d][ii] = g_KT[base + (size_t)d * HWN + ii];
    }
    __syncthreads();
    int tx = t & 15, ty = t >> 4;
    u64 acc[4][2];
    #pragma unroll
    for (int u = 0; u < 4; u++) { acc[u][0] = 0ull; acc[u][1] = 0ull; }
    #pragma unroll
    for (int d = 0; d < 64; d++) {
        float4 q4 = *(float4*)&qs[d][ty * 4];
        const u64* kp = (const u64*)&ks[d][tx * 4];
        u64 k0 = kp[0], k1 = kp[1];
        u64 qa[4] = {pk2(q4.x), pk2(q4.y), pk2(q4.z), pk2(q4.w)};
        #pragma unroll
        for (int u = 0; u < 4; u++) {
            fma2(acc[u][0], qa[u], k0);
            fma2(acc[u][1], qa[u], k1);
        }
    }
    size_t pre = ((size_t)((b * NHH + h) * HH) * WW + j) * PLEN + 64;
    #pragma unroll
    for (int u = 0; u < 4; u++) {
        int i = ty * 4 + u;
        float2 p0 = up2(acc[u][0]), p1 = up2(acc[u][1]);
        float4 o = make_float4(p0.x * SCALE, p0.y * SCALE, p1.x * SCALE, p1.y * SCALE);
        *(float4*)&g_P[pre + (size_t)i * (WW * PLEN) + tx * 4] = o;
    }
}

// =====================================================================
// Fused softmax loader: 4 lanes per query, 32 logits each, joint softmax
// over 128, keep half [keepLo ? k<64 : k>=64] normalized into psT[k][q].
// =====================================================================
__device__ __forceinline__ void softmax_half_to_smem(
    const float* __restrict__ qlog,    // 128 contiguous logits for this query
    int qidx, int laneInGrp, bool keepLo, float psT[64][68])
{
    float v[32];
    const float4* src = (const float4*)(qlog + laneInGrp * 32);
    #pragma unroll
    for (int r = 0; r < 8; r++) {
        float4 f = src[r];
        v[r * 4 + 0] = f.x; v[r * 4 + 1] = f.y;
        v[r * 4 + 2] = f.z; v[r * 4 + 3] = f.w;
    }
    float m = v[0];
    #pragma unroll
    for (int e = 1; e < 32; e++) m = fmaxf(m, v[e]);
    m = fmaxf(m, __shfl_xor_sync(0xffffffffu, m, 1));
    m = fmaxf(m, __shfl_xor_sync(0xffffffffu, m, 2));
    float s = 0.0f;
    #pragma unroll
    for (int e = 0; e < 32; e++) { v[e] = __expf(v[e] - m); s += v[e]; }
    s += __shfl_xor_sync(0xffffffffu, s, 1);
    s += __shfl_xor_sync(0xffffffffu, s, 2);
    float inv = 1.0f / s;
    int kBase = laneInGrp * 32;
    bool keep = keepLo ? (kBase < 64) : (kBase >= 64);
    if (keep) {
        int k0 = keepLo ? kBase : (kBase - 64);
        #pragma unroll
        for (int e = 0; e < 32; e++)
            psT[k0 + e][qidx] = v[e] * inv;
    }
}

// =====================================================================
// Kernel 6: row attention + fused softmax. block (i,h,b).
// =====================================================================
__global__ __launch_bounds__(256) void attn_row_kernel()
{
    int i = blockIdx.x, h = blockIdx.y, b = blockIdx.z;
    __shared__ float vsT[64][68];
    __shared__ float psT[64][68];
    size_t vbase = ((size_t)(b * DQKV + h * DHH)) * HWN + i * WW;
    size_t pbase = (((size_t)((b * NHH + h) * HH + i)) * WW) * PLEN;
    int t = threadIdx.x;
    // V tile (transposed to [k][d])
    #pragma unroll
    for (int r = 0; r < 16; r++) {
        int idx = r * 256 + t;
        int a = idx >> 6, k = idx & 63;
        vsT[k][a] = g_V[vbase + (size_t)a * HWN + k];
    }
    // softmax: query j = (t>>2), lane-in-group = t&3
    {
        int j = t >> 2;
        softmax_half_to_smem(g_P + pbase + (size_t)j * PLEN, j, t & 3, true, psT);
    }
    __syncthreads();
    int tx = t & 15, ty = t >> 4;
    u64 acc[4][2];
    #pragma unroll
    for (int u = 0; u < 4; u++) { acc[u][0] = 0ull; acc[u][1] = 0ull; }
    #pragma unroll
    for (int k = 0; k < 64; k++) {
        float4 v4 = *(float4*)&vsT[k][ty * 4];
        const u64* pp = (const u64*)&psT[k][tx * 4];
        u64 p0 = pp[0], p1 = pp[1];
        u64 va[4] = {pk2(v4.x), pk2(v4.y), pk2(v4.z), pk2(v4.w)};
        #pragma unroll
        for (int u = 0; u < 4; u++) {
            fma2(acc[u][0], va[u], p0);
            fma2(acc[u][1], va[u], p1);
        }
    }
    float av[4][4];
    #pragma unroll
    for (int u = 0; u < 4; u++) {
        float2 a0 = up2(acc[u][0]), a1 = up2(acc[u][1]);
        av[u][0] = a0.x; av[u][1] = a0.y; av[u][2] = a1.x; av[u][3] = a1.y;
    }
    int chb = h * DHH + ty * 4;
    #pragma unroll
    for (int cc = 0; cc < 4; cc++) {
        int p = i * WW + tx * 4 + cc;
        *(float4*)(g_A + ((size_t)b * HWN + p) * DQKV + chb) =
            make_float4(av[0][cc], av[1][cc], av[2][cc], av[3][cc]);
    }
}

// =====================================================================
// Kernel 7: column attention + fused softmax. block (j,h,b).
// =====================================================================
__global__ __launch_bounds__(256) void attn_col_kernel()
{
    int j = blockIdx.x, h = blockIdx.y, b = blockIdx.z;
    __shared__ float vsT[64][68];
    __shared__ float psT[64][68];
    size_t vbase = ((size_t)(b * DQKV + h * DHH)) * HWN + j * HH;
    size_t pbh   = ((size_t)((b * NHH + h) * HH)) * WW * PLEN;
    int t = threadIdx.x;
    #pragma unroll
    for (int r = 0; r < 16; r++) {
        int idx = r * 256 + t;
        int a = idx >> 6, k = idx & 63;
        vsT[k][a] = g_VT[vbase + (size_t)a * HWN + k];
    }
    // softmax: query i = (t>>2); logits at pbh + (i*64 + j)*128
    {
        int i = t >> 2;
        softmax_half_to_smem(g_P + pbh + ((size_t)i * WW + j) * PLEN,
                             i, t & 3, false, psT);
    }
    __syncthreads();
    int tx = t & 15, ty = t >> 4;
    u64 acc[4][2];
    #pragma unroll
    for (int u = 0; u < 4; u++) { acc[u][0] = 0ull; acc[u][1] = 0ull; }
    #pragma unroll
    for (int k = 0; k < 64; k++) {
        float4 v4 = *(float4*)&vsT[k][ty * 4];
        const u64* pp = (const u64*)&psT[k][tx * 4];
        u64 p0 = pp[0], p1 = pp[1];
        u64 va[4] = {pk2(v4.x), pk2(v4.y), pk2(v4.z), pk2(v4.w)};
        #pragma unroll
        for (int u = 0; u < 4; u++) {
            fma2(acc[u][0], va[u], p0);
            fma2(acc[u][1], va[u], p1);
        }
    }
    float av[4][4];
    #pragma unroll
    for (int u = 0; u < 4; u++) {
        float2 a0 = up2(acc[u][0]), a1 = up2(acc[u][1]);
        av[u][0] = a0.x; av[u][1] = a0.y; av[u][2] = a1.x; av[u][3] = a1.y;
    }
    int chb = h * DHH + ty * 4;
    #pragma unroll
    for (int cc = 0; cc < 4; cc++) {
        int p = (tx * 4 + cc) * WW + j;
        *(float4*)(g_AT + ((size_t)b * HWN + p) * DQKV + chb) =
            make_float4(av[0][cc], av[1][cc], av[2][cc], av[3][cc]);
    }
}

// =====================================================================
// Kernel 9: output projection + residual via mma.sync tf32.
// =====================================================================
__global__ __launch_bounds__(256, 2) void proj_mma(
    const float* __restrict__ x, const float* __restrict__ Wo,
    const float* __restrict__ bo, float* __restrict__ out)
{
    int pT = blockIdx.x, mT = blockIdx.y, b = blockIdx.z;
    int mOff = mT * 128;

    __shared__ uint32_t As[128][36];
    __shared__ uint32_t Bs[128][36];

    int t = threadIdx.x, lane = t & 31, wid = t >> 5;
    int g = lane >> 2, tig = lane & 3;
    int wm = (wid >> 2) * 64, wn = (wid & 3) * 32;

    const float* a2w = g_A  + ((size_t)b * HWN + (size_t)pT * 128) * DQKV;
    const float* a2h = g_AT + ((size_t)b * HWN + (size_t)pT * 128) * DQKV;

    float c[4][4][4];
    #pragma unroll
    for (int mi = 0; mi < 4; mi++)
        #pragma unroll
        for (int ni = 0; ni < 4; ni++)
            #pragma unroll
            for (int e = 0; e < 4; e++) c[mi][ni][e] = 0.0f;

    for (int c0 = 0; c0 < 16; c0++) {
        int kBase = c0 * 32;
        #pragma unroll
        for (int r = 0; r < 4; r++) {
            int idx = r * 256 + t;
            int row = idx >> 3, q = idx & 7;
            int k4 = kBase + q * 4;
            float4 va = *(const float4*)(Wo + (size_t)(mOff + row) * DQKV + k4);
            As[row][q * 4 + 0] = f2tf32(va.x);
            As[row][q * 4 + 1] = f2tf32(va.y);
            As[row][q * 4 + 2] = f2tf32(va.z);
            As[row][q * 4 + 3] = f2tf32(va.w);
            float4 vb = *(const float4*)(a2w + (size_t)row * DQKV + k4);
            float4 vh = *(const float4*)(a2h + (size_t)row * DQKV + k4);
            Bs[row][q * 4 + 0] = f2tf32(vb.x + vh.x);
            Bs[row][q * 4 + 1] = f2tf32(vb.y + vh.y);
            Bs[row][q * 4 + 2] = f2tf32(vb.z + vh.z);
            Bs[row][q * 4 + 3] = f2tf32(vb.w + vh.w);
        }
        __syncthreads();
        #pragma unroll
        for (int ks = 0; ks < 4; ks++) {
            int kk = ks * 8;
            uint32_t a[4][4], bfr[4][2];
            #pragma unroll
            for (int mi = 0; mi < 4; mi++) {
                int row = wm + mi * 16 + g;
                a[mi][0] = As[row][kk + tig];
                a[mi][1] = As[row + 8][kk + tig];
                a[mi][2] = As[row][kk + tig + 4];
                a[mi][3] = As[row + 8][kk + tig + 4];
            }
            #pragma unroll
            for (int ni = 0; ni < 4; ni++) {
                int col = wn + ni * 8 + g;
                bfr[ni][0] = Bs[col][kk + tig];
                bfr[ni][1] = Bs[col][kk + tig + 4];
            }
            #pragma unroll
            for (int mi = 0; mi < 4; mi++)
                #pragma unroll
                for (int ni = 0; ni < 4; ni++)
                    mma_tf32(c[mi][ni], a[mi], bfr[ni]);
        }
        __syncthreads();
    }

    #pragma unroll
    for (int mi = 0; mi < 4; mi++) {
        int row0 = wm + mi * 16 + g;
        int ch0 = mOff + row0;
        float bi0 = bo[ch0];
        float bi1 = bo[ch0 + 8];
        size_t base0 = ((size_t)b * CC + ch0) * HWN + (size_t)pT * 128;
        size_t base1 = base0 + (size_t)8 * HWN;
        #pragma unroll
        for (int ni = 0; ni < 4; ni++) {
            int col = wn + ni * 8 + tig * 2;
            float2 x0 = *(const float2*)(x + base0 + col);
            float2 x1 = *(const float2*)(x + base1 + col);
            float2 v0 = make_float2(c[mi][ni][0] + bi0 + x0.x,
                                    c[mi][ni][1] + bi0 + x0.y);
            float2 v1 = make_float2(c[mi][ni][2] + bi1 + x1.x,
                                    c[mi][ni][3] + bi1 + x1.y);
            *(float2*)(out + base0 + col) = v0;
            *(float2*)(out + base1 + col) = v1;
        }
    }
}

// =====================================================================
extern "C" void kernel_launch(void* const* d_in, const int* in_sizes, int n_in,
                              void* d_out, int out_size)
{
    const float* x   = (const float*)d_in[0];
    const float* pos = (const float*)d_in[1];
    const float* Wk  = (const float*)d_in[2];
    const float* bk  = (const float*)d_in[3];
    const float* Wq  = (const float*)d_in[4];
    const float* bq  = (const float*)d_in[5];
    const float* Wv  = (const float*)d_in[6];
    const float* bv  = (const float*)d_in[7];
    const float* Wo  = (const float*)d_in[8];
    const float* bo  = (const float*)d_in[9];
    float* out = (float*)d_out;

    xpose_x<<<dim3(64, 5, BB), 256>>>(x, pos);
    qkv_mma<<<dim3(32, 12, BB), 256>>>(Wq, bq, Wk, bk, Wv, bv);
    transpose3_kernel<<<dim3(BB * DQKV, 3), 256>>>();
    logits_row_kernel<<<dim3(HH, NHH, BB), 256>>>();
    logits_col_kernel<<<dim3(WW, NHH, BB), 256>>>();
    attn_row_kernel<<<dim3(HH, NHH, BB), 256>>>();
    attn_col_kernel<<<dim3(WW, NHH, BB), 256>>>();
    proj_mma<<<dim3(32, 2, BB), 256>>>(x, Wo, bo, out);
}